// round 10
// baseline (speedup 1.0000x reference)
#include <cuda_runtime.h>
#include <cuda_fp16.h>
#include <math.h>
#include <stdint.h>

#define N_ 16384
#define M_ 1024
#define D_ 256
#define EPS_ 1e-6f

// ---------------------------------------------------------------------------
// Scratch (device globals; allocations are forbidden)
// ---------------------------------------------------------------------------
__device__ __half g_xh[N_ * D_];   // fp16(x * fw)           8 MB
__device__ __half g_ph[M_ * D_];   // fp16(prototypes * fw)  0.5 MB
__device__ float  g_xn[N_];        // exact fp32 ||wx||^2
__device__ float  g_pn[M_];

// ---------------------------------------------------------------------------
// Helpers (family-portable PTX only: mma.sync / ldmatrix / cp.async)
// ---------------------------------------------------------------------------
__device__ __forceinline__ uint32_t smem_u32(const void* p) {
    uint32_t a;
    asm("{ .reg .u64 t; cvta.to.shared.u64 t, %1; cvt.u32.u64 %0, t; }" : "=r"(a) : "l"(p));
    return a;
}
#define CP_ASYNC16(saddr, gptr) \
    asm volatile("cp.async.cg.shared.global [%0], [%1], 16;" :: "r"(saddr), "l"(gptr))
#define CP_COMMIT() asm volatile("cp.async.commit_group;" ::: "memory")
#define CP_WAIT(n)  asm volatile("cp.async.wait_group %0;" :: "n"(n) : "memory")
#define LDSM4(r0, r1, r2, r3, addr) \
    asm volatile("ldmatrix.sync.aligned.m8n8.x4.shared.b16 {%0,%1,%2,%3}, [%4];" \
        : "=r"(r0), "=r"(r1), "=r"(r2), "=r"(r3) : "r"(addr))

__device__ __forceinline__ void mma16816(float c[4], const uint32_t a[4], const uint32_t b[2]) {
    asm volatile(
        "mma.sync.aligned.m16n8k16.row.col.f32.f16.f16.f32 "
        "{%0,%1,%2,%3}, {%4,%5,%6,%7}, {%8,%9}, {%0,%1,%2,%3};"
        : "+f"(c[0]), "+f"(c[1]), "+f"(c[2]), "+f"(c[3])
        : "r"(a[0]), "r"(a[1]), "r"(a[2]), "r"(a[3]), "r"(b[0]), "r"(b[1]));
}

// ---------------------------------------------------------------------------
// Prep (merged x + p): fold fw, fp16 convert, exact fp32 row norms.
// ---------------------------------------------------------------------------
__global__ void prep_kernel(const float* __restrict__ x, const float* __restrict__ p,
                            const float* __restrict__ fw) {
    const int w = blockIdx.x * 8 + (threadIdx.x >> 5);
    const int l = threadIdx.x & 31;
    const int isP = (w >= N_);
    const int r = isP ? (w - N_) : w;
    const float* src = isP ? p : x;
    __half* dst = isP ? g_ph : g_xh;
    float*  nrm = isP ? g_pn : g_xn;

    const float4* s4 = (const float4*)(src + (size_t)r * D_) + l * 2;
    const float4* f4 = (const float4*)fw + l * 2;
    float4 a0 = s4[0], a1 = s4[1];
    float4 w0 = f4[0], w1 = f4[1];
    float v[8] = {a0.x * w0.x, a0.y * w0.y, a0.z * w0.z, a0.w * w0.w,
                  a1.x * w1.x, a1.y * w1.y, a1.z * w1.z, a1.w * w1.w};
    __align__(16) __half h[8];
    float s = 0.f;
#pragma unroll
    for (int i = 0; i < 8; i++) {
        s += v[i] * v[i];
        h[i] = __float2half(v[i]);
    }
    *(uint4*)(dst + (size_t)r * D_ + l * 8) = *(uint4*)h;
#pragma unroll
    for (int o = 16; o > 0; o >>= 1) s += __shfl_xor_sync(0xffffffffu, s, o);
    if (l == 0) nrm[r] = s;
}

// ---------------------------------------------------------------------------
// GEMM: 128x128 CTA tile, 4 warps (2x2 grid of 64x64 warp tiles), BK=64,
// 3-stage cp.async pipeline, ldmatrix.x4, fused rsqrt/exp epilogue.
// 1.5x less smem fragment-read traffic than the 8-warp 32x64 layout.
// SMEM rows padded to 144B (conflict-free ldmatrix: banks 4r..4r+3).
// ---------------------------------------------------------------------------
#define BM 128
#define BN 128
#define BKT 64
#define NKT (D_ / BKT)
#define NTHREADS 128
#define ROW_BYTES 144
#define TILE_BYTES (128 * ROW_BYTES)       // 18432 per operand
#define STAGE_BYTES (2 * TILE_BYTES)       // 36864
#define SMEM_TOTAL (3 * STAGE_BYTES)       // 110592 -> 2 CTAs/SM

__global__ __launch_bounds__(NTHREADS, 2)
void gemm_kernel(const float* __restrict__ temp_p, float* __restrict__ out) {
    extern __shared__ char smem[];
    const uint32_t sbase = smem_u32(smem);
    const int tid = threadIdx.x;
    const int wid = tid >> 5, lane = tid & 31;
    const int bm = blockIdx.y * BM;
    const int bn = blockIdx.x * BN;
    const int wm = wid & 1;   // 2 warps along M (64 rows each)
    const int wn = wid >> 1;  // 2 warps along N (64 cols each)
    const int lq = lane >> 2, lr = lane & 3;

    const float temp = __ldg(temp_p);

    const char* gA = (const char*)(g_xh + (size_t)bm * D_);
    const char* gB = (const char*)(g_ph + (size_t)bn * D_);

    // 2048 16B-chunks per stage (A:1024, B:1024); 128 threads -> 16 each
    auto load_stage = [&](int kt, int s) {
        const uint32_t sA = sbase + s * STAGE_BYTES;
        const int kbyte = kt * (BKT * 2);
#pragma unroll
        for (int t = 0; t < 8; t++) {
            const int idx = tid + t * NTHREADS;          // 0..1023 over A
            const int row = idx >> 3, ch = idx & 7;
            const int so = row * ROW_BYTES + ch * 16;
            const int go = row * 512 + kbyte + ch * 16;
            CP_ASYNC16(sA + so, gA + go);
            CP_ASYNC16(sA + TILE_BYTES + so, gB + go);
        }
    };

    // ldmatrix per-lane offsets (within stage)
    // A: 4 m16 tiles at rows wm*64 + mt*16
    const uint32_t aOff = (uint32_t)((wm * 64 + (lane & 15)) * ROW_BYTES + (lane >> 4) * 16);
    // B: 4 pairs of n8 tiles at rows wn*64 + pr*16
    const uint32_t bOff = (uint32_t)(TILE_BYTES +
        (wn * 64 + ((lane >> 4) << 3) + (lane & 7)) * ROW_BYTES + ((lane >> 3) & 1) * 16);

    float c[4][8][4];
#pragma unroll
    for (int mt = 0; mt < 4; mt++)
#pragma unroll
        for (int nt = 0; nt < 8; nt++)
#pragma unroll
            for (int j = 0; j < 4; j++) c[mt][nt][j] = 0.f;

    auto compute = [&](int s) {
        const uint32_t stg = sbase + s * STAGE_BYTES;
#pragma unroll
        for (int ks = 0; ks < 4; ks++) {
            uint32_t a[4][4], b[8][2];
            const uint32_t ksb = ks * 32;
#pragma unroll
            for (int mt = 0; mt < 4; mt++)
                LDSM4(a[mt][0], a[mt][1], a[mt][2], a[mt][3],
                      stg + aOff + mt * (16 * ROW_BYTES) + ksb);
#pragma unroll
            for (int pr = 0; pr < 4; pr++)
                LDSM4(b[2 * pr][0], b[2 * pr][1], b[2 * pr + 1][0], b[2 * pr + 1][1],
                      stg + bOff + pr * (16 * ROW_BYTES) + ksb);
#pragma unroll
            for (int mt = 0; mt < 4; mt++)
#pragma unroll
                for (int nt = 0; nt < 8; nt++)
                    mma16816(c[mt][nt], a[mt], b[nt]);
        }
    };

    // ---- 3-stage pipeline, NKT = 4, fully unrolled ----
    load_stage(0, 0); CP_COMMIT();
    load_stage(1, 1); CP_COMMIT();

    CP_WAIT(1); __syncthreads();           // tile 0 ready
    load_stage(2, 2); CP_COMMIT();
    compute(0);

    CP_WAIT(1); __syncthreads();           // tile 1 ready; stage0 free
    load_stage(3, 0); CP_COMMIT();
    compute(1);

    CP_WAIT(1); __syncthreads();           // tile 2 ready
    compute(2);

    CP_WAIT(0); __syncthreads();           // tile 3 ready
    compute(0);                            // tile 3 lives in stage 0

    // ---- fused epilogue: sq -> dist (rsqrt) -> sim; streaming stores ----
    float xn[4][2], pn[8][2];
#pragma unroll
    for (int mt = 0; mt < 4; mt++) {
        const int r = bm + wm * 64 + mt * 16 + lq;
        xn[mt][0] = g_xn[r];
        xn[mt][1] = g_xn[r + 8];
    }
#pragma unroll
    for (int nt = 0; nt < 8; nt++) {
        const int cc = bn + wn * 64 + nt * 8 + lr * 2;
        pn[nt][0] = g_pn[cc];
        pn[nt][1] = g_pn[cc + 1];
    }

    float* sim_out = out;
    float* dst_out = out + (size_t)N_ * M_;

#pragma unroll
    for (int mt = 0; mt < 4; mt++) {
#pragma unroll
        for (int p = 0; p < 2; p++) {
            const int row = bm + wm * 64 + mt * 16 + p * 8 + lq;
            const size_t rbase = (size_t)row * M_;
#pragma unroll
            for (int nt = 0; nt < 8; nt++) {
                const int col = bn + wn * 64 + nt * 8 + lr * 2;
                float2 sv, dv;
#pragma unroll
                for (int j = 0; j < 2; j++) {
                    const float dot = c[mt][nt][p * 2 + j];
                    const float sq = fmaxf(xn[mt][p] + pn[nt][j] - 2.0f * dot, 0.0f) + EPS_;
                    const float d = sq * rsqrtf(sq);   // sqrt(sq), sq >= eps > 0
                    ((float*)&dv)[j] = d;
                    ((float*)&sv)[j] = __expf(-temp * d);
                }
                __stcs((float2*)(sim_out + rbase + col), sv);
                __stcs((float2*)(dst_out + rbase + col), dv);
            }
        }
    }
}

// ---------------------------------------------------------------------------
extern "C" void kernel_launch(void* const* d_in, const int* in_sizes, int n_in,
                              void* d_out, int out_size) {
    const float* x    = (const float*)d_in[0];
    const float* p    = (const float*)d_in[1];
    const float* fw   = (const float*)d_in[2];
    const float* temp = (const float*)d_in[3];
    float* out = (float*)d_out;

    cudaFuncSetAttribute(gemm_kernel, cudaFuncAttributeMaxDynamicSharedMemorySize, SMEM_TOTAL);

    prep_kernel<<<(N_ + M_) / 8, 256>>>(x, p, fw);
    gemm_kernel<<<dim3(M_ / BN, N_ / BM), NTHREADS, SMEM_TOTAL>>>(temp, out);
}

// round 14
// speedup vs baseline: 1.0135x; 1.0135x over previous
#include <cuda_runtime.h>
#include <cuda_fp16.h>
#include <math.h>
#include <stdint.h>

#define N_ 16384
#define M_ 1024
#define D_ 256
#define EPS_ 1e-6f

// ---------------------------------------------------------------------------
// Scratch (device globals; allocations are forbidden)
// ---------------------------------------------------------------------------
__device__ __half g_xh[N_ * D_];   // fp16(x * fw)           8 MB
__device__ __half g_ph[M_ * D_];   // fp16(prototypes * fw)  0.5 MB
__device__ float  g_xn[N_];        // exact fp32 ||wx||^2
__device__ float  g_pn[M_];

// ---------------------------------------------------------------------------
// Helpers (family-portable PTX only: mma.sync / ldmatrix / cp.async)
// ---------------------------------------------------------------------------
__device__ __forceinline__ uint32_t smem_u32(const void* p) {
    uint32_t a;
    asm("{ .reg .u64 t; cvta.to.shared.u64 t, %1; cvt.u32.u64 %0, t; }" : "=r"(a) : "l"(p));
    return a;
}
#define CP_ASYNC16(saddr, gptr) \
    asm volatile("cp.async.cg.shared.global [%0], [%1], 16;" :: "r"(saddr), "l"(gptr))
#define CP_COMMIT() asm volatile("cp.async.commit_group;" ::: "memory")
#define CP_WAIT(n)  asm volatile("cp.async.wait_group %0;" :: "n"(n) : "memory")
#define LDSM4(r0, r1, r2, r3, addr) \
    asm volatile("ldmatrix.sync.aligned.m8n8.x4.shared.b16 {%0,%1,%2,%3}, [%4];" \
        : "=r"(r0), "=r"(r1), "=r"(r2), "=r"(r3) : "r"(addr))

__device__ __forceinline__ void mma16816(float c[4], const uint32_t a[4], const uint32_t b[2]) {
    asm volatile(
        "mma.sync.aligned.m16n8k16.row.col.f32.f16.f16.f32 "
        "{%0,%1,%2,%3}, {%4,%5,%6,%7}, {%8,%9}, {%0,%1,%2,%3};"
        : "+f"(c[0]), "+f"(c[1]), "+f"(c[2]), "+f"(c[3])
        : "r"(a[0]), "r"(a[1]), "r"(a[2]), "r"(a[3]), "r"(b[0]), "r"(b[1]));
}

// ---------------------------------------------------------------------------
// Prep (merged x + p): fold fw, fp16 convert, exact fp32 row norms.
// ---------------------------------------------------------------------------
__global__ void prep_kernel(const float* __restrict__ x, const float* __restrict__ p,
                            const float* __restrict__ fw) {
    const int w = blockIdx.x * 8 + (threadIdx.x >> 5);
    const int l = threadIdx.x & 31;
    const int isP = (w >= N_);
    const int r = isP ? (w - N_) : w;
    const float* src = isP ? p : x;
    __half* dst = isP ? g_ph : g_xh;
    float*  nrm = isP ? g_pn : g_xn;

    const float4* s4 = (const float4*)(src + (size_t)r * D_) + l * 2;
    const float4* f4 = (const float4*)fw + l * 2;
    float4 a0 = s4[0], a1 = s4[1];
    float4 w0 = f4[0], w1 = f4[1];
    float v[8] = {a0.x * w0.x, a0.y * w0.y, a0.z * w0.z, a0.w * w0.w,
                  a1.x * w1.x, a1.y * w1.y, a1.z * w1.z, a1.w * w1.w};
    __align__(16) __half h[8];
    float s = 0.f;
#pragma unroll
    for (int i = 0; i < 8; i++) {
        s += v[i] * v[i];
        h[i] = __float2half(v[i]);
    }
    *(uint4*)(dst + (size_t)r * D_ + l * 8) = *(uint4*)h;
#pragma unroll
    for (int o = 16; o > 0; o >>= 1) s += __shfl_xor_sync(0xffffffffu, s, o);
    if (l == 0) nrm[r] = s;
}

// ---------------------------------------------------------------------------
// GEMM: 128x64 CTA tile, 8 warps (4x2 grid of 32x32 warp tiles), BK=64,
// 2-stage cp.async pipeline. No minBlocks reg cap (avoids pathological ptxas
// spill search); 3 CTAs/SM achieved via smem iff natural regs <= 84.
// ldmatrix.x4, rsqrt/exp epilogue, streaming stores.
// SMEM rows padded to 144B (conflict-free ldmatrix: banks 4r..4r+3).
// ---------------------------------------------------------------------------
#define BM 128
#define BN 64
#define BKT 64
#define NKT (D_ / BKT)
#define NTHREADS 256
#define ROW_BYTES 144
#define A_ROWS 128
#define ROWS_TOT 192                        // A:128 + B:64
#define TILE_A (A_ROWS * ROW_BYTES)         // 18432
#define STAGE_BYTES (ROWS_TOT * ROW_BYTES)  // 27648
#define SMEM_TOTAL (2 * STAGE_BYTES)        // 55296 -> 3 CTAs/SM by smem

__global__ __launch_bounds__(NTHREADS)
void gemm_kernel(const float* __restrict__ temp_p, float* __restrict__ out) {
    extern __shared__ char smem[];
    const uint32_t sbase = smem_u32(smem);
    const int tid = threadIdx.x;
    const int wid = tid >> 5, lane = tid & 31;
    const int bm = blockIdx.y * BM;
    const int bn = blockIdx.x * BN;
    const int wm = wid & 3;   // 4 warps along M (32 rows each)
    const int wn = wid >> 2;  // 2 warps along N (32 cols each)
    const int lq = lane >> 2, lr = lane & 3;

    const float temp = __ldg(temp_p);

    const char* gA = (const char*)(g_xh + (size_t)bm * D_);
    const char* gB = (const char*)(g_ph + (size_t)bn * D_);

    // Unified loader: 192 rows x 8 chunks = 1536 chunks; 256 threads x 6.
    auto load_stage = [&](int kt, int s) {
        const uint32_t sS = sbase + s * STAGE_BYTES;
        const int kbyte = kt * (BKT * 2);
#pragma unroll
        for (int t = 0; t < 6; t++) {
            const int idx = tid + t * NTHREADS;
            const int row = idx >> 3, ch = idx & 7;
            const char* gsrc = (row < A_ROWS) ? (gA + row * 512)
                                              : (gB + (row - A_ROWS) * 512);
            CP_ASYNC16(sS + row * ROW_BYTES + ch * 16, gsrc + kbyte + ch * 16);
        }
    };

    // ldmatrix per-lane offsets (within stage) — same lane math as R8 (verified)
    const uint32_t aOff = (uint32_t)((wm * 32 + (lane & 15)) * ROW_BYTES + (lane >> 4) * 16);
    const uint32_t bOff = (uint32_t)(TILE_A +
        (wn * 32 + ((lane >> 4) << 3) + (lane & 7)) * ROW_BYTES + ((lane >> 3) & 1) * 16);

    float c[2][4][4];
#pragma unroll
    for (int mt = 0; mt < 2; mt++)
#pragma unroll
        for (int nt = 0; nt < 4; nt++)
#pragma unroll
            for (int j = 0; j < 4; j++) c[mt][nt][j] = 0.f;

    auto compute = [&](int s) {
        const uint32_t stg = sbase + s * STAGE_BYTES;
#pragma unroll
        for (int ks = 0; ks < 4; ks++) {
            uint32_t a[2][4], b[4][2];
            const uint32_t ksb = ks * 32;
#pragma unroll
            for (int mt = 0; mt < 2; mt++)
                LDSM4(a[mt][0], a[mt][1], a[mt][2], a[mt][3],
                      stg + aOff + mt * (16 * ROW_BYTES) + ksb);
#pragma unroll
            for (int pr = 0; pr < 2; pr++)
                LDSM4(b[2 * pr][0], b[2 * pr][1], b[2 * pr + 1][0], b[2 * pr + 1][1],
                      stg + bOff + pr * (16 * ROW_BYTES) + ksb);
#pragma unroll
            for (int mt = 0; mt < 2; mt++)
#pragma unroll
                for (int nt = 0; nt < 4; nt++)
                    mma16816(c[mt][nt], a[mt], b[nt]);
        }
    };

    // ---- 2-stage pipeline, NKT = 4 ----
    load_stage(0, 0); CP_COMMIT();
#pragma unroll
    for (int kt = 0; kt < NKT; kt++) {
        if (kt + 1 < NKT) {
            load_stage(kt + 1, (kt + 1) & 1);
            CP_COMMIT();
            CP_WAIT(1);
        } else {
            CP_WAIT(0);
        }
        __syncthreads();
        compute(kt & 1);
        __syncthreads();
    }

    // ---- fused epilogue: sq -> dist (rsqrt) -> sim; streaming stores ----
    float xn[2][2], pn[4][2];
#pragma unroll
    for (int mt = 0; mt < 2; mt++) {
        const int r = bm + wm * 32 + mt * 16 + lq;
        xn[mt][0] = g_xn[r];
        xn[mt][1] = g_xn[r + 8];
    }
#pragma unroll
    for (int nt = 0; nt < 4; nt++) {
        const int cc = bn + wn * 32 + nt * 8 + lr * 2;
        pn[nt][0] = g_pn[cc];
        pn[nt][1] = g_pn[cc + 1];
    }

    float* sim_out = out;
    float* dst_out = out + (size_t)N_ * M_;

#pragma unroll
    for (int mt = 0; mt < 2; mt++) {
#pragma unroll
        for (int p = 0; p < 2; p++) {
            const int row = bm + wm * 32 + mt * 16 + p * 8 + lq;
            const size_t rbase = (size_t)row * M_;
#pragma unroll
            for (int nt = 0; nt < 4; nt++) {
                const int col = bn + wn * 32 + nt * 8 + lr * 2;
                float2 sv, dv;
#pragma unroll
                for (int j = 0; j < 2; j++) {
                    const float dot = c[mt][nt][p * 2 + j];
                    const float sq = fmaxf(xn[mt][p] + pn[nt][j] - 2.0f * dot, 0.0f) + EPS_;
                    const float d = sq * rsqrtf(sq);   // sqrt(sq), sq >= eps > 0
                    ((float*)&dv)[j] = d;
                    ((float*)&sv)[j] = __expf(-temp * d);
                }
                __stcs((float2*)(sim_out + rbase + col), sv);
                __stcs((float2*)(dst_out + rbase + col), dv);
            }
        }
    }
}

// ---------------------------------------------------------------------------
extern "C" void kernel_launch(void* const* d_in, const int* in_sizes, int n_in,
                              void* d_out, int out_size) {
    const float* x    = (const float*)d_in[0];
    const float* p    = (const float*)d_in[1];
    const float* fw   = (const float*)d_in[2];
    const float* temp = (const float*)d_in[3];
    float* out = (float*)d_out;

    cudaFuncSetAttribute(gemm_kernel, cudaFuncAttributeMaxDynamicSharedMemorySize, SMEM_TOTAL);

    prep_kernel<<<(N_ + M_) / 8, 256>>>(x, p, fw);
    gemm_kernel<<<dim3(M_ / BN, N_ / BM), NTHREADS, SMEM_TOTAL>>>(temp, out);
}